// round 16
// baseline (speedup 1.0000x reference)
#include <cuda_runtime.h>
#include <cuda_bf16.h>
#include <math.h>
#include <stdint.h>

#define BB   2
#define HH   8
#define LL   4096
#define DMM  512
#define DHH  64
#define NBB  64
#define BSS  64
#define KPQ  9
#define GK   512

__device__ float g_q[BB*HH*LL*DHH];
__device__ float g_k[BB*HH*LL*DHH];
__device__ float g_v[BB*HH*LL*DHH];
__device__ float g_qproj[BB*HH*NBB*DHH];
__device__ float g_kproj[BB*HH*NBB*DHH];
__device__ float g_pbias[HH*NBB*NBB];
__device__ int   g_sel[BB*HH*NBB*KPQ];
__device__ float g_sparse[BB*HH*LL*DHH];
__device__ float g_kv[BB*HH*DHH*DHH];
__device__ float g_ksum[BB*HH*DHH];
__device__ __nv_bfloat16 g_xhi[BB*LL*DMM];
__device__ __nv_bfloat16 g_xmi[BB*LL*DMM];
__device__ __nv_bfloat16 g_xlo[BB*LL*DMM];
__device__ __nv_bfloat16 g_whi[4*DMM*DMM];
__device__ __nv_bfloat16 g_wmi[4*DMM*DMM];
__device__ __nv_bfloat16 g_wlo[4*DMM*DMM];

__device__ __forceinline__ uint32_t smem_u32(const void* p) {
    uint32_t a;
    asm("{ .reg .u64 t; cvta.to.shared.u64 t, %1; cvt.u32.u64 %0, t; }" : "=r"(a) : "l"(p));
    return a;
}
#define LDMX4(r0,r1,r2,r3,addr) \
    asm volatile("ldmatrix.sync.aligned.m8n8.x4.shared.b16 {%0,%1,%2,%3}, [%4];" \
        : "=r"(r0), "=r"(r1), "=r"(r2), "=r"(r3) : "r"(addr))
#define LDMX2T(r0,r1,addr) \
    asm volatile("ldmatrix.sync.aligned.m8n8.x2.trans.shared.b16 {%0,%1}, [%2];" \
        : "=r"(r0), "=r"(r1) : "r"(addr))
#define MMA16816(c, a, b0, b1) \
    asm volatile("mma.sync.aligned.m16n8k16.row.col.f32.bf16.bf16.f32 " \
        "{%0,%1,%2,%3}, {%4,%5,%6,%7}, {%8,%9}, {%0,%1,%2,%3};" \
        : "+f"((c)[0]), "+f"((c)[1]), "+f"((c)[2]), "+f"((c)[3]) \
        : "r"((a)[0]), "r"((a)[1]), "r"((a)[2]), "r"((a)[3]), "r"(b0), "r"(b1))
#define MMAS8(c, a0,a1,a2,a3, b0,b1) \
    asm volatile("mma.sync.aligned.m16n8k32.row.col.s32.s8.s8.s32 " \
        "{%0,%1,%2,%3}, {%4,%5,%6,%7}, {%8,%9}, {%0,%1,%2,%3};" \
        : "+r"((c)[0]), "+r"((c)[1]), "+r"((c)[2]), "+r"((c)[3]) \
        : "r"(a0), "r"(a1), "r"(a2), "r"(a3), "r"(b0), "r"(b1))
#define CPA16(smaddr, gptr) \
    asm volatile("cp.async.cg.shared.global [%0], [%1], 16;" :: "r"(smaddr), "l"(gptr))
#define CPCOMMIT() asm volatile("cp.async.commit_group;" ::: "memory")
#define CPWAIT1()  asm volatile("cp.async.wait_group 1;" ::: "memory")

__device__ __forceinline__ void split3(float x, __nv_bfloat16& h, __nv_bfloat16& m,
                                       __nv_bfloat16& l) {
    h = __float2bfloat16_rn(x);
    float r1 = x - __bfloat162float(h);
    m = __float2bfloat16_rn(r1);
    l = __float2bfloat16_rn(r1 - __bfloat162float(m));
}

// ---------------- fp32 -> (bf16 hi, mid, lo) ----------------
__global__ void cvt3_kernel(const float* __restrict__ src,
                            __nv_bfloat16* __restrict__ hi,
                            __nv_bfloat16* __restrict__ mi,
                            __nv_bfloat16* __restrict__ lo, int n4) {
    int i = blockIdx.x * blockDim.x + threadIdx.x;
    if (i >= n4) return;
    float4 v = ((const float4*)src)[i];
    __nv_bfloat16 h[4], m[4], l[4];
    float xs[4] = {v.x, v.y, v.z, v.w};
#pragma unroll
    for (int c = 0; c < 4; c++) split3(xs[c], h[c], m[c], l[c]);
    ((uint2*)hi)[i] = *(uint2*)h;
    ((uint2*)mi)[i] = *(uint2*)m;
    ((uint2*)lo)[i] = *(uint2*)l;
}

// ---- 3-term split-bf16 MMA GEMM, per-k32-chunk compensation, cp.async double-buffer ----
#define TSTRIDE 40
#define TILE_ELE (128*TSTRIDE)
#define TILEB    (TILE_ELE*2)
#define BUF_ELE  (6*TILE_ELE)
#define MMA_SMEM (2*BUF_ELE*2)

__global__ void __launch_bounds__(512) mma_gemm_kernel(
        const __nv_bfloat16* __restrict__ ahi, const __nv_bfloat16* __restrict__ ami,
        const __nv_bfloat16* __restrict__ alo,
        const __nv_bfloat16* __restrict__ bhi, const __nv_bfloat16* __restrict__ bmi,
        const __nv_bfloat16* __restrict__ blo,
        float* __restrict__ out0, float* __restrict__ out1, float* __restrict__ out2,
        int mode) {
    extern __shared__ __align__(16) __nv_bfloat16 smb[];
    int t = threadIdx.x;
    int wid = t >> 5, lane = t & 31;
    int wm = wid & 3, wn = wid >> 2;
    int m0 = blockIdx.y << 7, n0 = blockIdx.x << 7;
    uint32_t smem_base = smem_u32(smb);

    float macc[2][4][4];
#pragma unroll
    for (int i = 0; i < 2; i++)
#pragma unroll
        for (int j = 0; j < 4; j++)
#pragma unroll
            for (int c = 0; c < 4; c++) macc[i][j][c] = 0.f;

    const int lr = t >> 2, lq = t & 3;
    uint32_t aRow = lane & 15;
    uint32_t aCol = ((lane >> 4) & 1) << 3;
    uint32_t bRow = (((lane >> 4) & 1) << 3) + (lane & 7);
    uint32_t bCol = ((lane >> 3) & 1) << 3;

    {
        size_t ao = (size_t)(m0 + lr) * GK + lq * 8;
        size_t bo = (size_t)(n0 + lr) * GK + lq * 8;
        uint32_t sb = smem_base + (lr*TSTRIDE + lq*8) * 2;
        CPA16(sb + 0*TILEB, ahi + ao); CPA16(sb + 1*TILEB, ami + ao); CPA16(sb + 2*TILEB, alo + ao);
        CPA16(sb + 3*TILEB, bhi + bo); CPA16(sb + 4*TILEB, bmi + bo); CPA16(sb + 5*TILEB, blo + bo);
    }
    CPCOMMIT();

    for (int kc = 0; kc < 16; kc++) {
        if (kc < 15) {
            int kg = (kc + 1) << 5;
            size_t ao = (size_t)(m0 + lr) * GK + kg + lq * 8;
            size_t bo = (size_t)(n0 + lr) * GK + kg + lq * 8;
            uint32_t sb = smem_base + ((kc + 1) & 1) * (BUF_ELE*2) + (lr*TSTRIDE + lq*8) * 2;
            CPA16(sb + 0*TILEB, ahi + ao); CPA16(sb + 1*TILEB, ami + ao); CPA16(sb + 2*TILEB, alo + ao);
            CPA16(sb + 3*TILEB, bhi + bo); CPA16(sb + 4*TILEB, bmi + bo); CPA16(sb + 5*TILEB, blo + bo);
        }
        CPCOMMIT();
        CPWAIT1();
        __syncthreads();

        __nv_bfloat16* buf = smb + (kc & 1) * BUF_ELE;
        __nv_bfloat16* sAh = buf;
        __nv_bfloat16* sAm = buf + TILE_ELE;
        __nv_bfloat16* sAl = buf + 2*TILE_ELE;
        __nv_bfloat16* sBh = buf + 3*TILE_ELE;
        __nv_bfloat16* sBm = buf + 4*TILE_ELE;
        __nv_bfloat16* sBl = buf + 5*TILE_ELE;

        float cacc[2][4][4];
#pragma unroll
        for (int i = 0; i < 2; i++)
#pragma unroll
            for (int j = 0; j < 4; j++)
#pragma unroll
                for (int c = 0; c < 4; c++) cacc[i][j][c] = 0.f;

#pragma unroll
        for (int ks = 0; ks < 2; ks++) {
            int kk = ks << 4;
            uint32_t ah[2][4], am[2][4], al[2][4];
#pragma unroll
            for (int mt = 0; mt < 2; mt++) {
                int ar = (wm*32 + mt*16 + aRow) * TSTRIDE + kk + aCol;
                LDMX4(ah[mt][0], ah[mt][1], ah[mt][2], ah[mt][3], smem_u32(&sAh[ar]));
                LDMX4(am[mt][0], am[mt][1], am[mt][2], am[mt][3], smem_u32(&sAm[ar]));
                LDMX4(al[mt][0], al[mt][1], al[mt][2], al[mt][3], smem_u32(&sAl[ar]));
            }
#pragma unroll
            for (int np = 0; np < 2; np++) {
                uint32_t bh4[4], bm4[4], bl4[4];
                int br = (wn*32 + np*16 + bRow) * TSTRIDE + kk + bCol;
                LDMX4(bh4[0], bh4[1], bh4[2], bh4[3], smem_u32(&sBh[br]));
                LDMX4(bm4[0], bm4[1], bm4[2], bm4[3], smem_u32(&sBm[br]));
                LDMX4(bl4[0], bl4[1], bl4[2], bl4[3], smem_u32(&sBl[br]));
                float* c00 = cacc[0][np*2];
                float* c01 = cacc[0][np*2+1];
                float* c10 = cacc[1][np*2];
                float* c11 = cacc[1][np*2+1];
                MMA16816(c00, ah[0], bh4[0], bh4[1]); MMA16816(c10, ah[1], bh4[0], bh4[1]);
                MMA16816(c01, ah[0], bh4[2], bh4[3]); MMA16816(c11, ah[1], bh4[2], bh4[3]);
                MMA16816(c00, ah[0], bm4[0], bm4[1]); MMA16816(c10, ah[1], bm4[0], bm4[1]);
                MMA16816(c01, ah[0], bm4[2], bm4[3]); MMA16816(c11, ah[1], bm4[2], bm4[3]);
                MMA16816(c00, am[0], bh4[0], bh4[1]); MMA16816(c10, am[1], bh4[0], bh4[1]);
                MMA16816(c01, am[0], bh4[2], bh4[3]); MMA16816(c11, am[1], bh4[2], bh4[3]);
                MMA16816(c00, am[0], bm4[0], bm4[1]); MMA16816(c10, am[1], bm4[0], bm4[1]);
                MMA16816(c01, am[0], bm4[2], bm4[3]); MMA16816(c11, am[1], bm4[2], bm4[3]);
                MMA16816(c00, ah[0], bl4[0], bl4[1]); MMA16816(c10, ah[1], bl4[0], bl4[1]);
                MMA16816(c01, ah[0], bl4[2], bl4[3]); MMA16816(c11, ah[1], bl4[2], bl4[3]);
                MMA16816(c00, al[0], bh4[0], bh4[1]); MMA16816(c10, al[1], bh4[0], bh4[1]);
                MMA16816(c01, al[0], bh4[2], bh4[3]); MMA16816(c11, al[1], bh4[2], bh4[3]);
            }
        }
#pragma unroll
        for (int i = 0; i < 2; i++)
#pragma unroll
            for (int j = 0; j < 4; j++)
#pragma unroll
                for (int c = 0; c < 4; c++) macc[i][j][c] += cacc[i][j][c];
        __syncthreads();
    }

#pragma unroll
    for (int mt = 0; mt < 2; mt++)
#pragma unroll
        for (int nt = 0; nt < 4; nt++) {
            int mg = m0 + wm*32 + mt*16 + (lane >> 2);
            int ng = n0 + wn*32 + nt*8 + ((lane & 3) << 1);
            float* c = macc[mt][nt];
            if (mode == 0) {
                *(float2*)(out0 + (size_t)mg * DMM + ng) = make_float2(c[0], c[1]);
                *(float2*)(out0 + (size_t)(mg + 8) * DMM + ng) = make_float2(c[2], c[3]);
            } else {
                int hh = ng >> 6;
                float* buf2 = (hh < 8) ? out0 : (hh < 16) ? out1 : out2;
                int h = hh & 7, col = ng & 63;
                int b = mg >> 12, l = mg & 4095;
                float* dp = buf2 + (((size_t)(b*HH + h) * LL + l) << 6) + col;
                *(float2*)dp = make_float2(c[0], c[1]);
                *(float2*)(dp + (8 << 6)) = make_float2(c[2], c[3]);
            }
        }
}

// ================= router / pooling =================
__global__ void pool_proj_kernel(const float* __restrict__ Wrq, const float* __restrict__ Wrk) {
    int qb = blockIdx.x, bh = blockIdx.y;
    int t = threadIdx.x;
    int d = t & 63, g = t >> 6;
    __shared__ float sq[4][64], sk[4][64];
    __shared__ float qp[64], kp[64];
    const float* qb_ = g_q + ((size_t)bh * LL + qb * BSS + g * 16) * DHH;
    const float* kb_ = g_k + ((size_t)bh * LL + qb * BSS + g * 16) * DHH;
    float aq = 0.f, ak = 0.f;
#pragma unroll 4
    for (int i = 0; i < 16; i++) { aq += qb_[i*DHH + d]; ak += kb_[i*DHH + d]; }
    sq[g][d] = aq; sk[g][d] = ak;
    __syncthreads();
    if (t < 64) {
        qp[d] = (sq[0][d]+sq[1][d]+sq[2][d]+sq[3][d]) * (1.f / BSS);
        kp[d] = (sk[0][d]+sk[1][d]+sk[2][d]+sk[3][d]) * (1.f / BSS);
    }
    __syncthreads();
    float pq = 0.f, pk2 = 0.f;
#pragma unroll 4
    for (int e = g*16; e < g*16 + 16; e++) {
        pq  += qp[e] * Wrq[d*DHH + e];
        pk2 += kp[e] * Wrk[d*DHH + e];
    }
    sq[g][d] = pq; sk[g][d] = pk2;
    __syncthreads();
    if (t < 64) {
        g_qproj[((size_t)bh * NBB + qb) * DHH + d] = sq[0][d]+sq[1][d]+sq[2][d]+sq[3][d];
        g_kproj[((size_t)bh * NBB + qb) * DHH + d] = sk[0][d]+sk[1][d]+sk[2][d]+sk[3][d];
    }
}

__global__ void pool_bias_kernel(const float* __restrict__ pb) {
    int h = blockIdx.y;
    int qb = blockIdx.x >> 6, kb = blockIdx.x & 63;
    const float* base = pb + ((size_t)h * LL + qb * BSS) * LL + kb * BSS;
    int t = threadIdx.x;
    int j = t & 63, i0 = t >> 6;
    float s = 0.f;
    for (int i = i0; i < BSS; i += 2) s += base[(size_t)i * LL + j];
    __shared__ float red[128];
    red[t] = s;
    __syncthreads();
    if (t < 64) red[t] += red[t + 64];
    __syncthreads();
    if (t < 32) {
        float v = red[t] + red[t + 32];
        for (int o = 16; o; o >>= 1) v += __shfl_xor_sync(0xffffffffu, v, o);
        if (t == 0) g_pbias[((size_t)h * NBB + qb) * NBB + kb] = v * (1.f / (BSS * BSS));
    }
}

__global__ void router_topk_kernel(const float* __restrict__ bscale_p) {
    __shared__ float sc[NBB][NBB];
    int bh = blockIdx.x;
    int h = bh & 7;
    float bsc = *bscale_p;
    const float* qp = g_qproj + (size_t)bh * NBB * DHH;
    const float* kp = g_kproj + (size_t)bh * NBB * DHH;
    for (int e = threadIdx.x; e < NBB * NBB; e += 256) {
        int qb = e >> 6, kb = e & 63;
        float s = 0.f;
        for (int d = 0; d < DHH; d++) s += qp[qb*DHH + d] * kp[kb*DHH + d];
        sc[qb][kb] = s * 0.125f + bsc * g_pbias[((size_t)h * NBB + qb) * NBB + kb];
    }
    __syncthreads();
    int warp = threadIdx.x >> 5, lane = threadIdx.x & 31;
    for (int r = warp; r < NBB; r += 8) {
        float v0 = sc[r][lane], v1 = sc[r][lane + 32];
        int i0 = lane, i1 = lane + 32;
        for (int tk = 0; tk < KPQ; tk++) {
            float bv; int bi;
            if (v0 > v1 || (v0 == v1 && i0 < i1)) { bv = v0; bi = i0; }
            else { bv = v1; bi = i1; }
            for (int off = 16; off; off >>= 1) {
                float ov = __shfl_xor_sync(0xffffffffu, bv, off);
                int   oi = __shfl_xor_sync(0xffffffffu, bi, off);
                if (ov > bv || (ov == bv && oi < bi)) { bv = ov; bi = oi; }
            }
            if (lane == 0) g_sel[((size_t)bh * NBB + r) * KPQ + tk] = bi;
            if (i0 == bi) v0 = -INFINITY;
            if (i1 == bi) v1 = -INFINITY;
        }
    }
}

// ====== sparse attention: quarter-split (16 q-rows/CTA), 3 CTAs/SM ======
__device__ __forceinline__ float fq_clip(float r) {
    return fminf(fmaxf(r, -128.f), 127.f);
}

#define SST 580
#define QPW 20
#define WQS 72
#define VS  72
// words: S 16*580 + qp 1280 + kp 1280 + sq 64 + sk 64 + stats 48 + wq 576 + vh 2304 + vm 2304
#define SP_WORDS (16*SST + 64*QPW + 64*QPW + 64 + 64 + 48 + 576 + 2304 + 2304)
#define SP_SMEM (SP_WORDS * 4)

__device__ __forceinline__ void q8_pack(const float* __restrict__ src_base,
                                        uint32_t* __restrict__ dst,
                                        float* __restrict__ scl,
                                        int lrow, int lg) {
    const float* src = src_base + (size_t)lrow * DHH + lg * 16;
    float x[16];
    float mx = 0.f;
#pragma unroll
    for (int c = 0; c < 16; c += 4) {
        float4 v = *(const float4*)(src + c);
        x[c] = v.x; x[c+1] = v.y; x[c+2] = v.z; x[c+3] = v.w;
    }
#pragma unroll
    for (int c = 0; c < 16; c++) mx = fmaxf(mx, fabsf(x[c]));
    mx = fmaxf(mx, __shfl_xor_sync(0xffffffffu, mx, 1));
    mx = fmaxf(mx, __shfl_xor_sync(0xffffffffu, mx, 2));
    float scale = fmaxf(mx, 1e-8f) / 127.0f;
    if (lg == 0) scl[lrow] = scale;
#pragma unroll
    for (int w = 0; w < 4; w++) {
        int q0 = (int)fq_clip(rintf(x[w*4+0] / scale));
        int q1 = (int)fq_clip(rintf(x[w*4+1] / scale));
        int q2 = (int)fq_clip(rintf(x[w*4+2] / scale));
        int q3 = (int)fq_clip(rintf(x[w*4+3] / scale));
        dst[lrow*QPW + lg*4 + w] =
            (q0 & 0xFF) | ((q1 & 0xFF) << 8) | ((q2 & 0xFF) << 16) | ((q3 & 0xFF) << 24);
    }
}

__global__ void __launch_bounds__(256) sparse_attn_kernel(const float* __restrict__ pb) {
    extern __shared__ float sm[];
    float*    S    = sm;                          // [16][SST]
    uint32_t* qp   = (uint32_t*)(S + 16*SST);     // [64][QPW]
    uint32_t* kp   = qp + 64*QPW;
    float*    sq   = (float*)(kp + 64*QPW);       // [64]
    float*    sk   = sq + 64;
    float*    rowm = sk + 64;                     // [16]
    float*    rowz = rowm + 16;
    float*    rowsc= rowz + 16;
    __nv_bfloat16* wqb = (__nv_bfloat16*)(rowsc + 16); // [16][WQS]
    __nv_bfloat16* vhb = wqb + 16*WQS;                 // [64][VS]
    __nv_bfloat16* vmb = vhb + 64*VS;

    int qb = blockIdx.x, bh = blockIdx.y, h = bh & 7;
    int quart = blockIdx.z;
    int t = threadIdx.x, lane = t & 31, wid = t >> 5;
    int wn = wid;                                  // 8 n-warps
    int gid = lane >> 2, tq = lane & 3;
    int lrow = t >> 2, lg = t & 3;                 // 64-row ops
    int lrow16 = t >> 4, lg16 = t & 15;            // 16-row ops
    const int selbase = (bh*NBB + qb)*KPQ;
    int r0 = gid;                                  // local row 0..7 (pairs with r0+8)
    int qrow = quart*16 + r0;                      // global q row in block

    q8_pack(g_q + ((size_t)bh*LL + qb*BSS)*DHH, qp, sq, lrow, lg);

    for (int kb = 0; kb < KPQ; kb++) {
        int kidx = g_sel[selbase + kb];
        __syncthreads();
        q8_pack(g_k + ((size_t)bh*LL + (size_t)kidx*BSS)*DHH, kp, sk, lrow, lg);
        __syncthreads();
        uint32_t a0 = qp[qrow*QPW + tq],      a1 = qp[(qrow+8)*QPW + tq];
        uint32_t a2 = qp[qrow*QPW + tq+4],    a3 = qp[(qrow+8)*QPW + tq+4];
        uint32_t a4 = qp[qrow*QPW + tq+8],    a5 = qp[(qrow+8)*QPW + tq+8];
        uint32_t a6 = qp[qrow*QPW + tq+12],   a7 = qp[(qrow+8)*QPW + tq+12];
        int col = wn*8;
        int cb = (col + gid)*QPW;
        int c[4] = {0,0,0,0};
        MMAS8(c, a0,a1,a2,a3, kp[cb+tq],   kp[cb+tq+4]);
        MMAS8(c, a4,a5,a6,a7, kp[cb+tq+8], kp[cb+tq+12]);
        int j = col + tq*2;
        const float* bp = pb + ((size_t)h*LL + qb*BSS + quart*16 + r0)*LL + (size_t)kidx*BSS + j;
        float2 p0 = *(const float2*)bp;
        float2 p1 = *(const float2*)(bp + (size_t)8*LL);
        float si0 = sq[qrow], si1 = sq[qrow+8];
        float sj0 = sk[j],  sj1 = sk[j+1];
        int jj = kb*64 + j;
        *(float2*)&S[r0*SST + jj] =
            make_float2(si0*sj0*(float)c[0] + p0.x, si0*sj1*(float)c[1] + p0.y);
        *(float2*)&S[(r0+8)*SST + jj] =
            make_float2(si1*sj0*(float)c[2] + p1.x, si1*sj1*(float)c[3] + p1.y);
    }
    __syncthreads();

    // softmax stats: 16 rows, 16 threads/row
    {
        float m = -INFINITY;
        const float* srow = S + (size_t)lrow16*SST;
        for (int j = lg16; j < 576; j += 16) m = fmaxf(m, srow[j]);
        m = fmaxf(m, __shfl_xor_sync(0xffffffffu, m, 1));
        m = fmaxf(m, __shfl_xor_sync(0xffffffffu, m, 2));
        m = fmaxf(m, __shfl_xor_sync(0xffffffffu, m, 4));
        m = fmaxf(m, __shfl_xor_sync(0xffffffffu, m, 8));
        float z = 0.f;
        for (int j = lg16; j < 576; j += 16) z += expf(srow[j] - m);
        z += __shfl_xor_sync(0xffffffffu, z, 1);
        z += __shfl_xor_sync(0xffffffffu, z, 2);
        z += __shfl_xor_sync(0xffffffffu, z, 4);
        z += __shfl_xor_sync(0xffffffffu, z, 8);
        if (lg16 == 0) {
            rowm[lrow16] = m; rowz[lrow16] = z;
            rowsc[lrow16] = fmaxf(1.0f / z, 1e-8f) / 127.0f;
        }
    }

    // ---- W*V ----
    float accW[4];
#pragma unroll
    for (int c = 0; c < 4; c++) accW[c] = 0.f;

    for (int kb = 0; kb < KPQ; kb++) {
        int kidx = g_sel[selbase + kb];
        __syncthreads();
        // wq convert: 16 rows x 64 cols (16 threads/row, 4 cols each)
        {
            float m = rowm[lrow16], z = rowz[lrow16], sc = rowsc[lrow16];
            const float* srow = S + (size_t)lrow16*SST + kb*64 + lg16*4;
#pragma unroll
            for (int cc = 0; cc < 4; cc += 2) {
                float w0 = expf(srow[cc]   - m) / z;
                float w1 = expf(srow[cc+1] - m) / z;
                __nv_bfloat162 pr;
                pr.x = __float2bfloat16_rn(fq_clip(rintf(w0 / sc)));
                pr.y = __float2bfloat16_rn(fq_clip(rintf(w1 / sc)));
                *(__nv_bfloat162*)&wqb[lrow16*WQS + lg16*4 + cc] = pr;
            }
        }
        // v convert: 64 rows
        {
            const float* vsrc = g_v + ((size_t)bh*LL + (size_t)kidx*BSS + lrow)*DHH + lg*16;
            float x[16];
            float mx = 0.f;
#pragma unroll
            for (int c = 0; c < 16; c += 4) {
                float4 v = *(const float4*)(vsrc + c);
                x[c] = v.x; x[c+1] = v.y; x[c+2] = v.z; x[c+3] = v.w;
            }
#pragma unroll
            for (int c = 0; c < 16; c++) mx = fmaxf(mx, fabsf(x[c]));
            mx = fmaxf(mx, __shfl_xor_sync(0xffffffffu, mx, 1));
            mx = fmaxf(mx, __shfl_xor_sync(0xffffffffu, mx, 2));
            float scale = fmaxf(mx, 1e-8f) / 127.0f;
#pragma unroll
            for (int cc = 0; cc < 16; cc += 2) {
                float v0 = fq_clip(rintf(x[cc]   / scale)) * scale;
                float v1 = fq_clip(rintf(x[cc+1] / scale)) * scale;
                __nv_bfloat16 h0 = __float2bfloat16_rn(v0);
                __nv_bfloat16 h1 = __float2bfloat16_rn(v1);
                __nv_bfloat162 ph; ph.x = h0; ph.y = h1;
                __nv_bfloat162 pm;
                pm.x = __float2bfloat16_rn(v0 - __bfloat162float(h0));
                pm.y = __float2bfloat16_rn(v1 - __bfloat162float(h1));
                *(__nv_bfloat162*)&vhb[lrow*VS + lg*16 + cc] = ph;
                *(__nv_bfloat162*)&vmb[lrow*VS + lg*16 + cc] = pm;
            }
        }
        __syncthreads();
#pragma unroll
        for (int ks = 0; ks < 4; ks++) {
            uint32_t aw[4];
            uint32_t adA = smem_u32(&wqb[(lane & 15)*WQS + ks*16 + ((lane >> 4) & 1)*8]);
            LDMX4(aw[0], aw[1], aw[2], aw[3], adA);
            int col = wn*8;
            uint32_t b0, b1;
            LDMX2T(b0, b1, smem_u32(&vhb[(ks*16 + (lane & 15))*VS + col]));
            MMA16816(accW, aw, b0, b1);
            LDMX2T(b0, b1, smem_u32(&vmb[(ks*16 + (lane & 15))*VS + col]));
            MMA16816(accW, aw, b0, b1);
        }
    }

    float rs0 = rowsc[r0], rs1 = rowsc[r0+8];
    float* dst = g_sparse + ((size_t)bh*LL + qb*BSS + quart*16)*DHH;
    int d = wn*8 + tq*2;
    *(float2*)&dst[(size_t)r0*DHH + d] = make_float2(rs0*accW[0], rs0*accW[1]);
    *(float2*)&dst[(size_t)(r0+8)*DHH + d] = make_float2(rs1*accW[2], rs1*accW[3]);
}

// ================= linear branch + blend =================
#define FMA16(acc,a,b) { \
  acc[0][0]+=a.x*b.x; acc[0][1]+=a.x*b.y; acc[0][2]+=a.x*b.z; acc[0][3]+=a.x*b.w; \
  acc[1][0]+=a.y*b.x; acc[1][1]+=a.y*b.y; acc[1][2]+=a.y*b.z; acc[1][3]+=a.y*b.w; \
  acc[2][0]+=a.z*b.x; acc[2][1]+=a.z*b.y; acc[2][2]+=a.z*b.z; acc[2][3]+=a.z*b.w; \
  acc[3][0]+=a.w*b.x; acc[3][1]+=a.w*b.y; acc[3][2]+=a.w*b.z; acc[3][3]+=a.w*b.w; }

__global__ void linear_kv_kernel() {
    int bh = blockIdx.y;
    __shared__ float pk[64][68];
    __shared__ float vvs[64][68];
    __shared__ float ksred[64];
    int t = threadIdx.x;
    int tx = t & 15, ty = t >> 4;
    int lrow = t >> 2, lg = t & 3;
    float acc[4][4];
#pragma unroll
    for (int i = 0; i < 4; i++)
#pragma unroll
        for (int j = 0; j < 4; j++) acc[i][j] = 0.f;
    float ksp[16];
#pragma unroll
    for (int c = 0; c < 16; c++) ksp[c] = 0.f;
    if (t < 64) ksred[t] = 0.f;

    for (int sub = 0; sub < 4; sub++) {
        size_t l0 = (size_t)blockIdx.x * 256 + sub * 64;
        const float* ks = g_k + ((size_t)bh * LL + l0 + lrow) * DHH + lg * 16;
        const float* vs = g_v + ((size_t)bh * LL + l0 + lrow) * DHH + lg * 16;
        __syncthreads();
#pragma unroll
        for (int c = 0; c < 16; c += 4) {
            float4 kx = *(const float4*)(ks + c);
            float4 vx = *(const float4*)(vs + c);
            float p0 = kx.x > 0.f ? kx.x + 1.f : expm1f(kx.x) + 1.f;
            float p1 = kx.y > 0.f ? kx.y + 1.f : expm1f(kx.y) + 1.f;
            float p2 = kx.z > 0.f ? kx.z + 1.f : expm1f(kx.z) + 1.f;
            float p3 = kx.w > 0.f ? kx.w + 1.f : expm1f(kx.w) + 1.f;
            pk[lrow][lg*16 + c    ] = p0;
            pk[lrow][lg*16 + c + 1] = p1;
            pk[lrow][lg*16 + c + 2] = p2;
            pk[lrow][lg*16 + c + 3] = p3;
            ksp[c] += p0; ksp[c+1] += p1; ksp[c+2] += p2; ksp[c+3] += p3;
            *(float4*)&vvs[lrow][lg*16 + c] = vx;
        }
        __syncthreads();
#pragma unroll 8
        for (int l = 0; l < 64; l++) {
            float4 a = *(const float4*)&pk[l][ty << 2];
            float4 b = *(const float4*)&vvs[l][tx << 2];
            FMA16(acc, a, b);
        }
    }
    __syncthreads();
#pragma unroll
    for (int c = 0; c < 16; c++) atomicAdd(&ksred[lg*16 + c], ksp[c]);
    __syncthreads();
    float* kvo = g_kv + (size_t)bh * DHH * DHH;
#pragma unroll
    for (int di = 0; di < 4; di++)
#pragma unroll
        for (int mi = 0; mi < 4; mi++)
            atomicAdd(&kvo[((ty<<2) + di) * DHH + (tx<<2) + mi], acc[di][mi]);
    if (t < 64) atomicAdd(&g_ksum[(size_t)bh * DHH + t], ksred[t]);
}

__global__ void linear_out_blend_kernel(const float* __restrict__ alog) {
    int bh = blockIdx.y;
    int b = bh >> 3, h = bh & 7;
    __shared__ float kvs[64][64];
    __shared__ float kss[64];
    int t = threadIdx.x;
    for (int e = t; e < 4096; e += 256) kvs[e >> 6][e & 63] = g_kv[(size_t)bh * 4096 + e];
    if (t < 64) kss[t] = g_ksum[(size_t)bh * DHH + t];
    __syncthreads();
    float alpha = 1.f / (1.f + expf(-alog[h]));
    int warp = t >> 5, lane = t & 31;
    int l = blockIdx.x * 8 + warp;
    const float* qrow = g_q + ((size_t)bh * LL + l) * DHH;
    float x0 = qrow[lane], x1 = qrow[lane + 32];
    float p0 = x0 > 0.f ? x0 + 1.f : expm1f(x0) + 1.f;
    float p1 = x1 > 0.f ? x1 + 1.f : expm1f(x1) + 1.f;
    float den = p0 * kss[lane] + p1 * kss[lane + 32];
    for (int o = 16; o; o >>= 1) den += __shfl_xor_sync(0xffffffffu, den, o);
    float a0 = 0.f, a1 = 0.f;
#pragma unroll
    for (int d = 0; d < 64; d++) {
        float pv = (d < 32) ? __shfl_sync(0xffffffffu, p0, d)
                            : __shfl_sync(0xffffffffu, p1, d - 32);
        a0 += pv * kvs[d][lane];
        a1 += pv * kvs[d][lane + 32];
    }
    float dd = den + 1e-6f;
    const float* sp = g_sparse + ((size_t)bh * LL + l) * DHH;
    float o0 = alpha * sp[lane]      + (1.f - alpha) * (a0 / dd);
    float o1 = alpha * sp[lane + 32] + (1.f - alpha) * (a1 / dd);
    size_t base = ((size_t)b * LL + l) * DMM + h * DHH;
    __nv_bfloat16 hh0, mm0, ll0, hh1, mm1, ll1;
    split3(o0, hh0, mm0, ll0);
    split3(o1, hh1, mm1, ll1);
    g_xhi[base + lane] = hh0;      g_xhi[base + lane + 32] = hh1;
    g_xmi[base + lane] = mm0;      g_xmi[base + lane + 32] = mm1;
    g_xlo[base + lane] = ll0;      g_xlo[base + lane + 32] = ll1;
}

extern "C" void kernel_launch(void* const* d_in, const int* in_sizes, int n_in,
                              void* d_out, int out_size) {
    const float* hs  = (const float*)d_in[0];
    const float* pb  = (const float*)d_in[1];
    const float* Wq  = (const float*)d_in[2];
    const float* Wk  = (const float*)d_in[3];
    const float* Wv  = (const float*)d_in[4];
    const float* Wo  = (const float*)d_in[5];
    const float* Wrq = (const float*)d_in[6];
    const float* Wrk = (const float*)d_in[7];
    const float* bsc = (const float*)d_in[8];
    const float* alo = (const float*)d_in[9];
    float* out = (float*)d_out;

    static cudaStream_t s1 = 0;
    static cudaEvent_t evFork = 0, evQKV = 0, evPB = 0, evLKV = 0, evW = 0;
    if (!s1) {
        cudaStreamCreateWithFlags(&s1, cudaStreamNonBlocking);
        cudaEventCreateWithFlags(&evFork, cudaEventDisableTiming);
        cudaEventCreateWithFlags(&evQKV,  cudaEventDisableTiming);
        cudaEventCreateWithFlags(&evPB,   cudaEventDisableTiming);
        cudaEventCreateWithFlags(&evLKV,  cudaEventDisableTiming);
        cudaEventCreateWithFlags(&evW,    cudaEventDisableTiming);
        cudaFuncSetAttribute(sparse_attn_kernel,
                             cudaFuncAttributeMaxDynamicSharedMemorySize, SP_SMEM);
        cudaFuncSetAttribute(mma_gemm_kernel,
                             cudaFuncAttributeMaxDynamicSharedMemorySize, MMA_SMEM);
    }

    void *gq, *gk, *gv, *gkv, *gks, *gxh, *gxm, *gxl, *gwh, *gwm, *gwl;
    cudaGetSymbolAddress(&gq,  g_q);
    cudaGetSymbolAddress(&gk,  g_k);
    cudaGetSymbolAddress(&gv,  g_v);
    cudaGetSymbolAddress(&gkv, g_kv);
    cudaGetSymbolAddress(&gks, g_ksum);
    cudaGetSymbolAddress(&gxh, g_xhi);
    cudaGetSymbolAddress(&gxm, g_xmi);
    cudaGetSymbolAddress(&gxl, g_xlo);
    cudaGetSymbolAddress(&gwh, g_whi);
    cudaGetSymbolAddress(&gwm, g_wmi);
    cudaGetSymbolAddress(&gwl, g_wlo);
    __nv_bfloat16* xhi = (__nv_bfloat16*)gxh;
    __nv_bfloat16* xmi = (__nv_bfloat16*)gxm;
    __nv_bfloat16* xlo = (__nv_bfloat16*)gxl;
    __nv_bfloat16* whi = (__nv_bfloat16*)gwh;
    __nv_bfloat16* wmi = (__nv_bfloat16*)gwm;
    __nv_bfloat16* wlo = (__nv_bfloat16*)gwl;

    // ---- fork: weight cvt3s + pool_bias on s1 (both depend only on inputs) ----
    cudaEventRecord(evFork, 0);
    cudaStreamWaitEvent(s1, evFork, 0);
    const int NW4 = DMM*DMM/4;
    cvt3_kernel<<<(NW4+255)/256, 256, 0, s1>>>(Wq, whi,             wmi,             wlo,             NW4);
    cvt3_kernel<<<(NW4+255)/256, 256, 0, s1>>>(Wk, whi +   DMM*DMM, wmi +   DMM*DMM, wlo +   DMM*DMM, NW4);
    cvt3_kernel<<<(NW4+255)/256, 256, 0, s1>>>(Wv, whi + 2*DMM*DMM, wmi + 2*DMM*DMM, wlo + 2*DMM*DMM, NW4);
    cvt3_kernel<<<(NW4+255)/256, 256, 0, s1>>>(Wo, whi + 3*DMM*DMM, wmi + 3*DMM*DMM, wlo + 3*DMM*DMM, NW4);
    cudaEventRecord(evW, s1);
    pool_bias_kernel<<<dim3(NBB*NBB, HH), 128, 0, s1>>>(pb);
    cudaEventRecord(evPB, s1);

    cudaMemsetAsync(gkv, 0, sizeof(float) * BB*HH*DHH*DHH);
    cudaMemsetAsync(gks, 0, sizeof(float) * BB*HH*DHH);

    const int NX4 = BB*LL*DMM/4;
    cvt3_kernel<<<(NX4+255)/256, 256>>>(hs, xhi, xmi, xlo, NX4);
    cudaStreamWaitEvent(0, evW, 0);

    // fused QKV via compensated split-bf16 MMA (N=1536, BHLD scatter)
    mma_gemm_kernel<<<dim3(12, 64), 512, MMA_SMEM>>>(
        xhi, xmi, xlo, whi, wmi, wlo, (float*)gq, (float*)gk, (float*)gv, 1);
    cudaEventRecord(evQKV, 0);

    // ---- s1: linear_kv depends only on g_k/g_v ----
    cudaStreamWaitEvent(s1, evQKV, 0);
    linear_kv_kernel<<<dim3(LL/256, BB*HH), 256, 0, s1>>>();
    cudaEventRecord(evLKV, s1);

    // ---- s0: router chain + sparse attention (quarter split, 3 CTAs/SM) ----
    pool_proj_kernel<<<dim3(NBB, BB*HH), 256>>>(Wrq, Wrk);
    cudaStreamWaitEvent(0, evPB, 0);
    router_topk_kernel<<<BB*HH, 256>>>(bsc);
    sparse_attn_kernel<<<dim3(NBB, BB*HH, 4), 256, SP_SMEM>>>(pb);

    // ---- join: blend (writes bf16 splits directly) then Wo GEMM ----
    cudaStreamWaitEvent(0, evLKV, 0);
    linear_out_blend_kernel<<<dim3(LL/8, BB*HH), 256>>>(alo);
    mma_gemm_kernel<<<dim3(4, 64), 512, MMA_SMEM>>>(
        xhi, xmi, xlo, whi + 3*DMM*DMM, wmi + 3*DMM*DMM, wlo + 3*DMM*DMM, out, out, out, 0);
}

// round 17
// speedup vs baseline: 1.2714x; 1.2714x over previous
#include <cuda_runtime.h>
#include <cuda_bf16.h>
#include <math.h>
#include <stdint.h>

#define BB   2
#define HH   8
#define LL   4096
#define DMM  512
#define DHH  64
#define NBB  64
#define BSS  64
#define KPQ  9
#define GK   512

__device__ float g_q[BB*HH*LL*DHH];
__device__ float g_k[BB*HH*LL*DHH];
__device__ float g_v[BB*HH*LL*DHH];
__device__ float g_qproj[BB*HH*NBB*DHH];
__device__ float g_kproj[BB*HH*NBB*DHH];
__device__ float g_pbias[HH*NBB*NBB];
__device__ int   g_sel[BB*HH*NBB*KPQ];
__device__ float g_sparse[BB*HH*LL*DHH];
__device__ float g_kv[BB*HH*DHH*DHH];
__device__ float g_ksum[BB*HH*DHH];
__device__ __nv_bfloat16 g_xhi[BB*LL*DMM];
__device__ __nv_bfloat16 g_xmi[BB*LL*DMM];
__device__ __nv_bfloat16 g_xlo[BB*LL*DMM];
__device__ __nv_bfloat16 g_whi[4*DMM*DMM];
__device__ __nv_bfloat16 g_wmi[4*DMM*DMM];
__device__ __nv_bfloat16 g_wlo[4*DMM*DMM];
// precomputed packs
__device__ uint32_t g_q8[BB*HH*LL*16];
__device__ uint32_t g_k8[BB*HH*LL*16];
__device__ float    g_qsc[BB*HH*LL];
__device__ float    g_ksc[BB*HH*LL];
__device__ __nv_bfloat16 g_vh[BB*HH*LL*DHH];
__device__ __nv_bfloat16 g_vm[BB*HH*LL*DHH];

__device__ __forceinline__ uint32_t smem_u32(const void* p) {
    uint32_t a;
    asm("{ .reg .u64 t; cvta.to.shared.u64 t, %1; cvt.u32.u64 %0, t; }" : "=r"(a) : "l"(p));
    return a;
}
#define LDMX4(r0,r1,r2,r3,addr) \
    asm volatile("ldmatrix.sync.aligned.m8n8.x4.shared.b16 {%0,%1,%2,%3}, [%4];" \
        : "=r"(r0), "=r"(r1), "=r"(r2), "=r"(r3) : "r"(addr))
#define LDMX2T(r0,r1,addr) \
    asm volatile("ldmatrix.sync.aligned.m8n8.x2.trans.shared.b16 {%0,%1}, [%2];" \
        : "=r"(r0), "=r"(r1) : "r"(addr))
#define MMA16816(c, a, b0, b1) \
    asm volatile("mma.sync.aligned.m16n8k16.row.col.f32.bf16.bf16.f32 " \
        "{%0,%1,%2,%3}, {%4,%5,%6,%7}, {%8,%9}, {%0,%1,%2,%3};" \
        : "+f"((c)[0]), "+f"((c)[1]), "+f"((c)[2]), "+f"((c)[3]) \
        : "r"((a)[0]), "r"((a)[1]), "r"((a)[2]), "r"((a)[3]), "r"(b0), "r"(b1))
#define MMAS8(c, a0,a1,a2,a3, b0,b1) \
    asm volatile("mma.sync.aligned.m16n8k32.row.col.s32.s8.s8.s32 " \
        "{%0,%1,%2,%3}, {%4,%5,%6,%7}, {%8,%9}, {%0,%1,%2,%3};" \
        : "+r"((c)[0]), "+r"((c)[1]), "+r"((c)[2]), "+r"((c)[3]) \
        : "r"(a0), "r"(a1), "r"(a2), "r"(a3), "r"(b0), "r"(b1))
#define CPA16(smaddr, gptr) \
    asm volatile("cp.async.cg.shared.global [%0], [%1], 16;" :: "r"(smaddr), "l"(gptr))
#define CPCOMMIT() asm volatile("cp.async.commit_group;" ::: "memory")
#define CPWAIT1()  asm volatile("cp.async.wait_group 1;" ::: "memory")

__device__ __forceinline__ void split3(float x, __nv_bfloat16& h, __nv_bfloat16& m,
                                       __nv_bfloat16& l) {
    h = __float2bfloat16_rn(x);
    float r1 = x - __bfloat162float(h);
    m = __float2bfloat16_rn(r1);
    l = __float2bfloat16_rn(r1 - __bfloat162float(m));
}

__global__ void cvt3_kernel(const float* __restrict__ src,
                            __nv_bfloat16* __restrict__ hi,
                            __nv_bfloat16* __restrict__ mi,
                            __nv_bfloat16* __restrict__ lo, int n4) {
    int i = blockIdx.x * blockDim.x + threadIdx.x;
    if (i >= n4) return;
    float4 v = ((const float4*)src)[i];
    __nv_bfloat16 h[4], m[4], l[4];
    float xs[4] = {v.x, v.y, v.z, v.w};
#pragma unroll
    for (int c = 0; c < 4; c++) split3(xs[c], h[c], m[c], l[c]);
    ((uint2*)hi)[i] = *(uint2*)h;
    ((uint2*)mi)[i] = *(uint2*)m;
    ((uint2*)lo)[i] = *(uint2*)l;
}

// ---- 3-term split-bf16 MMA GEMM (unchanged from R15) ----
#define TSTRIDE 40
#define TILE_ELE (128*TSTRIDE)
#define TILEB    (TILE_ELE*2)
#define BUF_ELE  (6*TILE_ELE)
#define MMA_SMEM (2*BUF_ELE*2)

__global__ void __launch_bounds__(512) mma_gemm_kernel(
        const __nv_bfloat16* __restrict__ ahi, const __nv_bfloat16* __restrict__ ami,
        const __nv_bfloat16* __restrict__ alo,
        const __nv_bfloat16* __restrict__ bhi, const __nv_bfloat16* __restrict__ bmi,
        const __nv_bfloat16* __restrict__ blo,
        float* __restrict__ out0, float* __restrict__ out1, float* __restrict__ out2,
        int mode) {
    extern __shared__ __align__(16) __nv_bfloat16 smb[];
    int t = threadIdx.x;
    int wid = t >> 5, lane = t & 31;
    int wm = wid & 3, wn = wid >> 2;
    int m0 = blockIdx.y << 7, n0 = blockIdx.x << 7;
    uint32_t smem_base = smem_u32(smb);

    float macc[2][4][4];
#pragma unroll
    for (int i = 0; i < 2; i++)
#pragma unroll
        for (int j = 0; j < 4; j++)
#pragma unroll
            for (int c = 0; c < 4; c++) macc[i][j][c] = 0.f;

    const int lr = t >> 2, lq = t & 3;
    uint32_t aRow = lane & 15;
    uint32_t aCol = ((lane >> 4) & 1) << 3;
    uint32_t bRow = (((lane >> 4) & 1) << 3) + (lane & 7);
    uint32_t bCol = ((lane >> 3) & 1) << 3;

    {
        size_t ao = (size_t)(m0 + lr) * GK + lq * 8;
        size_t bo = (size_t)(n0 + lr) * GK + lq * 8;
        uint32_t sb = smem_base + (lr*TSTRIDE + lq*8) * 2;
        CPA16(sb + 0*TILEB, ahi + ao); CPA16(sb + 1*TILEB, ami + ao); CPA16(sb + 2*TILEB, alo + ao);
        CPA16(sb + 3*TILEB, bhi + bo); CPA16(sb + 4*TILEB, bmi + bo); CPA16(sb + 5*TILEB, blo + bo);
    }
    CPCOMMIT();

    for (int kc = 0; kc < 16; kc++) {
        if (kc < 15) {
            int kg = (kc + 1) << 5;
            size_t ao = (size_t)(m0 + lr) * GK + kg + lq * 8;
            size_t bo = (size_t)(n0 + lr) * GK + kg + lq * 8;
            uint32_t sb = smem_base + ((kc + 1) & 1) * (BUF_ELE*2) + (lr*TSTRIDE + lq*8) * 2;
            CPA16(sb + 0*TILEB, ahi + ao); CPA16(sb + 1*TILEB, ami + ao); CPA16(sb + 2*TILEB, alo + ao);
            CPA16(sb + 3*TILEB, bhi + bo); CPA16(sb + 4*TILEB, bmi + bo); CPA16(sb + 5*TILEB, blo + bo);
        }
        CPCOMMIT();
        CPWAIT1();
        __syncthreads();

        __nv_bfloat16* buf = smb + (kc & 1) * BUF_ELE;
        __nv_bfloat16* sAh = buf;
        __nv_bfloat16* sAm = buf + TILE_ELE;
        __nv_bfloat16* sAl = buf + 2*TILE_ELE;
        __nv_bfloat16* sBh = buf + 3*TILE_ELE;
        __nv_bfloat16* sBm = buf + 4*TILE_ELE;
        __nv_bfloat16* sBl = buf + 5*TILE_ELE;

        float cacc[2][4][4];
#pragma unroll
        for (int i = 0; i < 2; i++)
#pragma unroll
            for (int j = 0; j < 4; j++)
#pragma unroll
                for (int c = 0; c < 4; c++) cacc[i][j][c] = 0.f;

#pragma unroll
        for (int ks = 0; ks < 2; ks++) {
            int kk = ks << 4;
            uint32_t ah[2][4], am[2][4], al[2][4];
#pragma unroll
            for (int mt = 0; mt < 2; mt++) {
                int ar = (wm*32 + mt*16 + aRow) * TSTRIDE + kk + aCol;
                LDMX4(ah[mt][0], ah[mt][1], ah[mt][2], ah[mt][3], smem_u32(&sAh[ar]));
                LDMX4(am[mt][0], am[mt][1], am[mt][2], am[mt][3], smem_u32(&sAm[ar]));
                LDMX4(al[mt][0], al[mt][1], al[mt][2], al[mt][3], smem_u32(&sAl[ar]));
            }
#pragma unroll
            for (int np = 0; np < 2; np++) {
                uint32_t bh4[4], bm4[4], bl4[4];
                int br = (wn*32 + np*16 + bRow) * TSTRIDE + kk + bCol;
                LDMX4(bh4[0], bh4[1], bh4[2], bh4[3], smem_u32(&sBh[br]));
                LDMX4(bm4[0], bm4[1], bm4[2], bm4[3], smem_u32(&sBm[br]));
                LDMX4(bl4[0], bl4[1], bl4[2], bl4[3], smem_u32(&sBl[br]));
                float* c00 = cacc[0][np*2];
                float* c01 = cacc[0][np*2+1];
                float* c10 = cacc[1][np*2];
                float* c11 = cacc[1][np*2+1];
                MMA16816(c00, ah[0], bh4[0], bh4[1]); MMA16816(c10, ah[1], bh4[0], bh4[1]);
                MMA16816(c01, ah[0], bh4[2], bh4[3]); MMA16816(c11, ah[1], bh4[2], bh4[3]);
                MMA16816(c00, ah[0], bm4[0], bm4[1]); MMA16816(c10, ah[1], bm4[0], bm4[1]);
                MMA16816(c01, ah[0], bm4[2], bm4[3]); MMA16816(c11, ah[1], bm4[2], bm4[3]);
                MMA16816(c00, am[0], bh4[0], bh4[1]); MMA16816(c10, am[1], bh4[0], bh4[1]);
                MMA16816(c01, am[0], bh4[2], bh4[3]); MMA16816(c11, am[1], bh4[2], bh4[3]);
                MMA16816(c00, am[0], bm4[0], bm4[1]); MMA16816(c10, am[1], bm4[0], bm4[1]);
                MMA16816(c01, am[0], bm4[2], bm4[3]); MMA16816(c11, am[1], bm4[2], bm4[3]);
                MMA16816(c00, ah[0], bl4[0], bl4[1]); MMA16816(c10, ah[1], bl4[0], bl4[1]);
                MMA16816(c01, ah[0], bl4[2], bl4[3]); MMA16816(c11, ah[1], bl4[2], bl4[3]);
                MMA16816(c00, al[0], bh4[0], bh4[1]); MMA16816(c10, al[1], bh4[0], bh4[1]);
                MMA16816(c01, al[0], bh4[2], bh4[3]); MMA16816(c11, al[1], bh4[2], bh4[3]);
            }
        }
#pragma unroll
        for (int i = 0; i < 2; i++)
#pragma unroll
            for (int j = 0; j < 4; j++)
#pragma unroll
                for (int c = 0; c < 4; c++) macc[i][j][c] += cacc[i][j][c];
        __syncthreads();
    }

#pragma unroll
    for (int mt = 0; mt < 2; mt++)
#pragma unroll
        for (int nt = 0; nt < 4; nt++) {
            int mg = m0 + wm*32 + mt*16 + (lane >> 2);
            int ng = n0 + wn*32 + nt*8 + ((lane & 3) << 1);
            float* c = macc[mt][nt];
            if (mode == 0) {
                *(float2*)(out0 + (size_t)mg * DMM + ng) = make_float2(c[0], c[1]);
                *(float2*)(out0 + (size_t)(mg + 8) * DMM + ng) = make_float2(c[2], c[3]);
            } else {
                int hh = ng >> 6;
                float* buf2 = (hh < 8) ? out0 : (hh < 16) ? out1 : out2;
                int h = hh & 7, col = ng & 63;
                int b = mg >> 12, l = mg & 4095;
                float* dp = buf2 + (((size_t)(b*HH + h) * LL + l) << 6) + col;
                *(float2*)dp = make_float2(c[0], c[1]);
                *(float2*)(dp + (8 << 6)) = make_float2(c[2], c[3]);
            }
        }
}

// ================= router / pooling (unchanged) =================
__global__ void pool_proj_kernel(const float* __restrict__ Wrq, const float* __restrict__ Wrk) {
    int qb = blockIdx.x, bh = blockIdx.y;
    int t = threadIdx.x;
    int d = t & 63, g = t >> 6;
    __shared__ float sq[4][64], sk[4][64];
    __shared__ float qp[64], kp[64];
    const float* qb_ = g_q + ((size_t)bh * LL + qb * BSS + g * 16) * DHH;
    const float* kb_ = g_k + ((size_t)bh * LL + qb * BSS + g * 16) * DHH;
    float aq = 0.f, ak = 0.f;
#pragma unroll 4
    for (int i = 0; i < 16; i++) { aq += qb_[i*DHH + d]; ak += kb_[i*DHH + d]; }
    sq[g][d] = aq; sk[g][d] = ak;
    __syncthreads();
    if (t < 64) {
        qp[d] = (sq[0][d]+sq[1][d]+sq[2][d]+sq[3][d]) * (1.f / BSS);
        kp[d] = (sk[0][d]+sk[1][d]+sk[2][d]+sk[3][d]) * (1.f / BSS);
    }
    __syncthreads();
    float pq = 0.f, pk2 = 0.f;
#pragma unroll 4
    for (int e = g*16; e < g*16 + 16; e++) {
        pq  += qp[e] * Wrq[d*DHH + e];
        pk2 += kp[e] * Wrk[d*DHH + e];
    }
    sq[g][d] = pq; sk[g][d] = pk2;
    __syncthreads();
    if (t < 64) {
        g_qproj[((size_t)bh * NBB + qb) * DHH + d] = sq[0][d]+sq[1][d]+sq[2][d]+sq[3][d];
        g_kproj[((size_t)bh * NBB + qb) * DHH + d] = sk[0][d]+sk[1][d]+sk[2][d]+sk[3][d];
    }
}

__global__ void pool_bias_kernel(const float* __restrict__ pb) {
    int h = blockIdx.y;
    int qb = blockIdx.x >> 6, kb = blockIdx.x & 63;
    const float* base = pb + ((size_t)h * LL + qb * BSS) * LL + kb * BSS;
    int t = threadIdx.x;
    int j = t & 63, i0 = t >> 6;
    float s = 0.f;
    for (int i = i0; i < BSS; i += 2) s += base[(size_t)i * LL + j];
    __shared__ float red[128];
    red[t] = s;
    __syncthreads();
    if (t < 64) red[t] += red[t + 64];
    __syncthreads();
    if (t < 32) {
        float v = red[t] + red[t + 32];
        for (int o = 16; o; o >>= 1) v += __shfl_xor_sync(0xffffffffu, v, o);
        if (t == 0) g_pbias[((size_t)h * NBB + qb) * NBB + kb] = v * (1.f / (BSS * BSS));
    }
}

__global__ void router_topk_kernel(const float* __restrict__ bscale_p) {
    __shared__ float sc[NBB][NBB];
    int bh = blockIdx.x;
    int h = bh & 7;
    float bsc = *bscale_p;
    const float* qp = g_qproj + (size_t)bh * NBB * DHH;
    const float* kp = g_kproj + (size_t)bh * NBB * DHH;
    for (int e = threadIdx.x; e < NBB * NBB; e += 256) {
        int qb = e >> 6, kb = e & 63;
        float s = 0.f;
        for (int d = 0; d < DHH; d++) s += qp[qb*DHH + d] * kp[kb*DHH + d];
        sc[qb][kb] = s * 0.125f + bsc * g_pbias[((size_t)h * NBB + qb) * NBB + kb];
    }
    __syncthreads();
    int warp = threadIdx.x >> 5, lane = threadIdx.x & 31;
    for (int r = warp; r < NBB; r += 8) {
        float v0 = sc[r][lane], v1 = sc[r][lane + 32];
        int i0 = lane, i1 = lane + 32;
        for (int tk = 0; tk < KPQ; tk++) {
            float bv; int bi;
            if (v0 > v1 || (v0 == v1 && i0 < i1)) { bv = v0; bi = i0; }
            else { bv = v1; bi = i1; }
            for (int off = 16; off; off >>= 1) {
                float ov = __shfl_xor_sync(0xffffffffu, bv, off);
                int   oi = __shfl_xor_sync(0xffffffffu, bi, off);
                if (ov > bv || (ov == bv && oi < bi)) { bv = ov; bi = oi; }
            }
            if (lane == 0) g_sel[((size_t)bh * NBB + r) * KPQ + tk] = bi;
            if (i0 == bi) v0 = -INFINITY;
            if (i1 == bi) v1 = -INFINITY;
        }
    }
}

// ====== pack kernel: hoisted fq packing (identical arithmetic to R15 in-kernel) ======
__device__ __forceinline__ float fq_clip(float r) {
    return fminf(fmaxf(r, -128.f), 127.f);
}

__global__ void __launch_bounds__(256) pack_kernel() {
    int blk = blockIdx.x, bh = blockIdx.y;
    int t = threadIdx.x;
    int lrow = t >> 2, lg = t & 3;
    size_t rowg = (size_t)bh*LL + (size_t)blk*BSS + lrow;

    // --- q ---
    {
        const float* src = g_q + rowg*DHH + lg*16;
        float x[16];
        float mx = 0.f;
#pragma unroll
        for (int c = 0; c < 16; c += 4) {
            float4 v = *(const float4*)(src + c);
            x[c] = v.x; x[c+1] = v.y; x[c+2] = v.z; x[c+3] = v.w;
        }
#pragma unroll
        for (int c = 0; c < 16; c++) mx = fmaxf(mx, fabsf(x[c]));
        mx = fmaxf(mx, __shfl_xor_sync(0xffffffffu, mx, 1));
        mx = fmaxf(mx, __shfl_xor_sync(0xffffffffu, mx, 2));
        float scale = fmaxf(mx, 1e-8f) / 127.0f;
        if (lg == 0) g_qsc[rowg] = scale;
#pragma unroll
        for (int w = 0; w < 4; w++) {
            int q0 = (int)fq_clip(rintf(x[w*4+0] / scale));
            int q1 = (int)fq_clip(rintf(x[w*4+1] / scale));
            int q2 = (int)fq_clip(rintf(x[w*4+2] / scale));
            int q3 = (int)fq_clip(rintf(x[w*4+3] / scale));
            g_q8[rowg*16 + lg*4 + w] =
                (q0 & 0xFF) | ((q1 & 0xFF) << 8) | ((q2 & 0xFF) << 16) | ((q3 & 0xFF) << 24);
        }
    }
    // --- k ---
    {
        const float* src = g_k + rowg*DHH + lg*16;
        float x[16];
        float mx = 0.f;
#pragma unroll
        for (int c = 0; c < 16; c += 4) {
            float4 v = *(const float4*)(src + c);
            x[c] = v.x; x[c+1] = v.y; x[c+2] = v.z; x[c+3] = v.w;
        }
#pragma unroll
        for (int c = 0; c < 16; c++) mx = fmaxf(mx, fabsf(x[c]));
        mx = fmaxf(mx, __shfl_xor_sync(0xffffffffu, mx, 1));
        mx = fmaxf(mx, __shfl_xor_sync(0xffffffffu, mx, 2));
        float scale = fmaxf(mx, 1e-8f) / 127.0f;
        if (lg == 0) g_ksc[rowg] = scale;
#pragma unroll
        for (int w = 0; w < 4; w++) {
            int q0 = (int)fq_clip(rintf(x[w*4+0] / scale));
            int q1 = (int)fq_clip(rintf(x[w*4+1] / scale));
            int q2 = (int)fq_clip(rintf(x[w*4+2] / scale));
            int q3 = (int)fq_clip(rintf(x[w*4+3] / scale));
            g_k8[rowg*16 + lg*4 + w] =
                (q0 & 0xFF) | ((q1 & 0xFF) << 8) | ((q2 & 0xFF) << 16) | ((q3 & 0xFF) << 24);
        }
    }
    // --- v: fq + exact 2-term bf16 split ---
    {
        const float* src = g_v + rowg*DHH + lg*16;
        float x[16];
        float mx = 0.f;
#pragma unroll
        for (int c = 0; c < 16; c += 4) {
            float4 v = *(const float4*)(src + c);
            x[c] = v.x; x[c+1] = v.y; x[c+2] = v.z; x[c+3] = v.w;
        }
#pragma unroll
        for (int c = 0; c < 16; c++) mx = fmaxf(mx, fabsf(x[c]));
        mx = fmaxf(mx, __shfl_xor_sync(0xffffffffu, mx, 1));
        mx = fmaxf(mx, __shfl_xor_sync(0xffffffffu, mx, 2));
        float scale = fmaxf(mx, 1e-8f) / 127.0f;
#pragma unroll
        for (int cc = 0; cc < 16; cc += 2) {
            float v0 = fq_clip(rintf(x[cc]   / scale)) * scale;
            float v1 = fq_clip(rintf(x[cc+1] / scale)) * scale;
            __nv_bfloat16 h0 = __float2bfloat16_rn(v0);
            __nv_bfloat16 h1 = __float2bfloat16_rn(v1);
            __nv_bfloat162 ph; ph.x = h0; ph.y = h1;
            __nv_bfloat162 pm;
            pm.x = __float2bfloat16_rn(v0 - __bfloat162float(h0));
            pm.y = __float2bfloat16_rn(v1 - __bfloat162float(h1));
            *(__nv_bfloat162*)&g_vh[rowg*DHH + lg*16 + cc] = ph;
            *(__nv_bfloat162*)&g_vm[rowg*DHH + lg*16 + cc] = pm;
        }
    }
}

// ====== sparse attention: half-split, packs loaded from precomputed buffers ======
#define SST 580
#define QPW 20
#define WQS 72
#define VS  72
#define SP_WORDS (32*SST + 64*QPW + 64*QPW + 64 + 64 + 96 + 1152 + 2304 + 2304)
#define SP_SMEM (SP_WORDS * 4)

__global__ void __launch_bounds__(256) sparse_attn_kernel(const float* __restrict__ pb) {
    extern __shared__ float sm[];
    float*    S    = sm;                          // [32][SST]
    uint32_t* qp   = (uint32_t*)(S + 32*SST);     // [64][QPW]
    uint32_t* kp   = qp + 64*QPW;
    float*    sq   = (float*)(kp + 64*QPW);       // [64]
    float*    sk   = sq + 64;
    float*    rowm = sk + 64;                     // [32]
    float*    rowz = rowm + 32;
    float*    rowsc= rowz + 32;
    __nv_bfloat16* wqb = (__nv_bfloat16*)(rowsc + 32); // [32][WQS]
    __nv_bfloat16* vhb = wqb + 32*WQS;                 // [64][VS]
    __nv_bfloat16* vmb = vhb + 64*VS;

    int qb = blockIdx.x, bh = blockIdx.y, h = bh & 7;
    int half = blockIdx.z;
    int t = threadIdx.x, lane = t & 31, wid = t >> 5;
    int wm = wid & 1, wn = wid >> 1;
    int gid = lane >> 2, tq = lane & 3;
    int lrow = t >> 2, lg = t & 3;
    int lrow32 = t >> 3, lg8 = t & 7;
    const int selbase = (bh*NBB + qb)*KPQ;
    int r0 = wm*16 + gid;
    int qrow = half*32 + r0;

    // load precomputed q pack
    {
        size_t base = ((size_t)bh*LL + (size_t)qb*BSS + lrow)*16 + lg*4;
        uint4 qv = *(const uint4*)&g_q8[base];
        qp[lrow*QPW + lg*4 + 0] = qv.x;
        qp[lrow*QPW + lg*4 + 1] = qv.y;
        qp[lrow*QPW + lg*4 + 2] = qv.z;
        qp[lrow*QPW + lg*4 + 3] = qv.w;
        if (t < 64) sq[t] = g_qsc[(size_t)bh*LL + (size_t)qb*BSS + t];
    }

    for (int kb = 0; kb < KPQ; kb++) {
        int kidx = g_sel[selbase + kb];
        __syncthreads();
        {
            size_t base = ((size_t)bh*LL + (size_t)kidx*BSS + lrow)*16 + lg*4;
            uint4 kv = *(const uint4*)&g_k8[base];
            kp[lrow*QPW + lg*4 + 0] = kv.x;
            kp[lrow*QPW + lg*4 + 1] = kv.y;
            kp[lrow*QPW + lg*4 + 2] = kv.z;
            kp[lrow*QPW + lg*4 + 3] = kv.w;
            if (t < 64) sk[t] = g_ksc[(size_t)bh*LL + (size_t)kidx*BSS + t];
        }
        __syncthreads();
        uint32_t a0 = qp[qrow*QPW + tq],      a1 = qp[(qrow+8)*QPW + tq];
        uint32_t a2 = qp[qrow*QPW + tq+4],    a3 = qp[(qrow+8)*QPW + tq+4];
        uint32_t a4 = qp[qrow*QPW + tq+8],    a5 = qp[(qrow+8)*QPW + tq+8];
        uint32_t a6 = qp[qrow*QPW + tq+12],   a7 = qp[(qrow+8)*QPW + tq+12];
#pragma unroll
        for (int nt = 0; nt < 2; nt++) {
            int col = wn*16 + nt*8;
            int cb = (col + gid)*QPW;
            int c[4] = {0,0,0,0};
            MMAS8(c, a0,a1,a2,a3, kp[cb+tq],   kp[cb+tq+4]);
            MMAS8(c, a4,a5,a6,a7, kp[cb+tq+8], kp[cb+tq+12]);
            int j = col + tq*2;
            const float* bp = pb + ((size_t)h*LL + qb*BSS + half*32 + r0)*LL + (size_t)kidx*BSS + j;
            float2 p0 = *(const float2*)bp;
            float2 p1 = *(const float2*)(bp + (size_t)8*LL);
            float si0 = sq[qrow], si1 = sq[qrow+8];
            float sj0 = sk[j],  sj1 = sk[j+1];
            int jj = kb*64 + j;
            *(float2*)&S[r0*SST + jj] =
                make_float2(si0*sj0*(float)c[0] + p0.x, si0*sj1*(float)c[1] + p0.y);
            *(float2*)&S[(r0+8)*SST + jj] =
                make_float2(si1*sj0*(float)c[2] + p1.x, si1*sj1*(float)c[3] + p1.y);
        }
    }
    __syncthreads();

    {
        float m = -INFINITY;
        const float* srow = S + (size_t)lrow32*SST;
        for (int j = lg8; j < 576; j += 8) m = fmaxf(m, srow[j]);
        m = fmaxf(m, __shfl_xor_sync(0xffffffffu, m, 1));
        m = fmaxf(m, __shfl_xor_sync(0xffffffffu, m, 2));
        m = fmaxf(m, __shfl_xor_sync(0xffffffffu, m, 4));
        float z = 0.f;
        for (int j = lg8; j < 576; j += 8) z += expf(srow[j] - m);
        z += __shfl_xor_sync(0xffffffffu, z, 1);
        z += __shfl_xor_sync(0xffffffffu, z, 2);
        z += __shfl_xor_sync(0xffffffffu, z, 4);
        if (lg8 == 0) {
            rowm[lrow32] = m; rowz[lrow32] = z;
            rowsc[lrow32] = fmaxf(1.0f / z, 1e-8f) / 127.0f;
        }
    }
    __syncthreads();

    float accW[2][4];
#pragma unroll
    for (int nt = 0; nt < 2; nt++)
#pragma unroll
        for (int c = 0; c < 4; c++) accW[nt][c] = 0.f;

    for (int kb = 0; kb < KPQ; kb++) {
        int kidx = g_sel[selbase + kb];
        __syncthreads();
        {
            float m = rowm[lrow32], z = rowz[lrow32], sc = rowsc[lrow32];
            const float* srow = S + (size_t)lrow32*SST + kb*64 + lg8*8;
#pragma unroll
            for (int cc = 0; cc < 8; cc += 2) {
                float w0 = expf(srow[cc]   - m) / z;
                float w1 = expf(srow[cc+1] - m) / z;
                __nv_bfloat162 pr;
                pr.x = __float2bfloat16_rn(fq_clip(rintf(w0 / sc)));
                pr.y = __float2bfloat16_rn(fq_clip(rintf(w1 / sc)));
                *(__nv_bfloat162*)&wqb[lrow32*WQS + lg8*8 + cc] = pr;
            }
        }
        {
            size_t vb = ((size_t)bh*LL + (size_t)kidx*BSS + lrow)*DHH + lg*16;
            *(uint4*)&vhb[lrow*VS + lg*16]     = *(const uint4*)&g_vh[vb];
            *(uint4*)&vhb[lrow*VS + lg*16 + 8] = *(const uint4*)&g_vh[vb + 8];
            *(uint4*)&vmb[lrow*VS + lg*16]     = *(const uint4*)&g_vm[vb];
            *(uint4*)&vmb[lrow*VS + lg*16 + 8] = *(const uint4*)&g_vm[vb + 8];
        }
        __syncthreads();
#pragma unroll
        for (int ks = 0; ks < 4; ks++) {
            uint32_t aw[4];
            uint32_t adA = smem_u32(&wqb[(wm*16 + (lane & 15))*WQS + ks*16 + ((lane >> 4) & 1)*8]);
            LDMX4(aw[0], aw[1], aw[2], aw[3], adA);
#pragma unroll
            for (int nt = 0; nt < 2; nt++) {
                int col = wn*16 + nt*8;
                uint32_t b0, b1;
                LDMX2T(b0, b1, smem_u32(&vhb[(ks*16 + (lane & 15))*VS + col]));
                MMA16816(accW[nt], aw, b0, b1);
                LDMX2T(b0, b1, smem_u32(&vmb[(ks*16 + (lane & 15))*VS + col]));
                MMA16816(accW[nt], aw, b0, b1);
            }
        }
    }

    float rs0 = rowsc[r0], rs1 = rowsc[r0+8];
    float* dst = g_sparse + ((size_t)bh*LL + qb*BSS + half*32)*DHH;
#pragma unroll
    for (int nt = 0; nt < 2; nt++) {
        int d = wn*16 + nt*8 + tq*2;
        *(float2*)&dst[(size_t)r0*DHH + d] =
            make_float2(rs0*accW[nt][0], rs0*accW[nt][1]);
        *(float2*)&dst[(size_t)(r0+8)*DHH + d] =
            make_float2(rs1*accW[nt][2], rs1*accW[nt][3]);
    }
}

// ================= linear branch + blend (unchanged) =================
#define FMA16(acc,a,b) { \
  acc[0][0]+=a.x*b.x; acc[0][1]+=a.x*b.y; acc[0][2]+=a.x*b.z; acc[0][3]+=a.x*b.w; \
  acc[1][0]+=a.y*b.x; acc[1][1]+=a.y*b.y; acc[1][2]+=a.y*b.z; acc[1][3]+=a.y*b.w; \
  acc[2][0]+=a.z*b.x; acc[2][1]+=a.z*b.y; acc[2][2]+=a.z*b.z; acc[2][3]+=a.z*b.w; \
  acc[3][0]+=a.w*b.x; acc[3][1]+=a.w*b.y; acc[3][2]+=a.w*b.z; acc[3][3]+=a.w*b.w; }

__global__ void linear_kv_kernel() {
    int bh = blockIdx.y;
    __shared__ float pk[64][68];
    __shared__ float vvs[64][68];
    __shared__ float ksred[64];
    int t = threadIdx.x;
    int tx = t & 15, ty = t >> 4;
    int lrow = t >> 2, lg = t & 3;
    float acc[4][4];
#pragma unroll
    for (int i = 0; i < 4; i++)
#pragma unroll
        for (int j = 0; j < 4; j++) acc[i][j] = 0.f;
    float ksp[16];
#pragma unroll
    for (int c = 0; c < 16; c++) ksp[c] = 0.f;
    if (t < 64) ksred[t] = 0.f;

    for (int sub = 0; sub < 4; sub++) {
        size_t l0 = (size_t)blockIdx.x * 256 + sub * 64;
        const float* ks = g_k + ((size_t)bh * LL + l0 + lrow) * DHH + lg * 16;
        const float* vs = g_v + ((size_t)bh * LL + l0 + lrow) * DHH + lg * 16;
        __syncthreads();
#pragma unroll
        for (int c = 0; c < 16; c += 4) {
            float4 kx = *(const float4*)(ks + c);
            float4 vx = *(const float4*)(vs + c);
            float p0 = kx.x > 0.f ? kx.x + 1.f : expm1f(kx.x) + 1.f;
            float p1 = kx.y > 0.f ? kx.y + 1.f : expm1f(kx.y) + 1.f;
            float p2 = kx.z > 0.f ? kx.z + 1.f : expm1f(kx.z) + 1.f;
            float p3 = kx.w > 0.f ? kx.w + 1.f : expm1f(kx.w) + 1.f;
            pk[lrow][lg*16 + c    ] = p0;
            pk[lrow][lg*16 + c + 1] = p1;
            pk[lrow][lg*16 + c + 2] = p2;
            pk[lrow][lg*16 + c + 3] = p3;
            ksp[c] += p0; ksp[c+1] += p1; ksp[c+2] += p2; ksp[c+3] += p3;
            *(float4*)&vvs[lrow][lg*16 + c] = vx;
        }
        __syncthreads();
#pragma unroll 8
        for (int l = 0; l < 64; l++) {
            float4 a = *(const float4*)&pk[l][ty << 2];
            float4 b = *(const float4*)&vvs[l][tx << 2];
            FMA16(acc, a, b);
        }
    }
    __syncthreads();
#pragma unroll
    for (int c = 0; c < 16; c++) atomicAdd(&ksred[lg*16 + c], ksp[c]);
    __syncthreads();
    float* kvo = g_kv + (size_t)bh * DHH * DHH;
#pragma unroll
    for (int di = 0; di < 4; di++)
#pragma unroll
        for (int mi = 0; mi < 4; mi++)
            atomicAdd(&kvo[((ty<<2) + di) * DHH + (tx<<2) + mi], acc[di][mi]);
    if (t < 64) atomicAdd(&g_ksum[(size_t)bh * DHH + t], ksred[t]);
}

__global__ void linear_out_blend_kernel(const float* __restrict__ alog) {
    int bh = blockIdx.y;
    int b = bh >> 3, h = bh & 7;
    __shared__ float kvs[64][64];
    __shared__ float kss[64];
    int t = threadIdx.x;
    for (int e = t; e < 4096; e += 256) kvs[e >> 6][e & 63] = g_kv[(size_t)bh * 4096 + e];
    if (t < 64) kss[t] = g_ksum[(size_t)bh * DHH + t];
    __syncthreads();
    float alpha = 1.f / (1.f + expf(-alog[h]));
    int warp = t >> 5, lane = t & 31;
    int l = blockIdx.x * 8 + warp;
    const float* qrow = g_q + ((size_t)bh * LL + l) * DHH;
    float x0 = qrow[lane], x1 = qrow[lane + 32];
    float p0 = x0 > 0.f ? x0 + 1.f : expm1f(x0) + 1.f;
    float p1 = x1 > 0.f ? x1 + 1.f : expm1f(x1) + 1.f;
    float den = p0 * kss[lane] + p1 * kss[lane + 32];
    for (int o = 16; o; o >>= 1) den += __shfl_xor_sync(0xffffffffu, den, o);
    float a0 = 0.f, a1 = 0.f;
#pragma unroll
    for (int d = 0; d < 64; d++) {
        float pv = (d < 32) ? __shfl_sync(0xffffffffu, p0, d)
                            : __shfl_sync(0xffffffffu, p1, d - 32);
        a0 += pv * kvs[d][lane];
        a1 += pv * kvs[d][lane + 32];
    }
    float dd = den + 1e-6f;
    const float* sp = g_sparse + ((size_t)bh * LL + l) * DHH;
    float o0 = alpha * sp[lane]      + (1.f - alpha) * (a0 / dd);
    float o1 = alpha * sp[lane + 32] + (1.f - alpha) * (a1 / dd);
    size_t base = ((size_t)b * LL + l) * DMM + h * DHH;
    __nv_bfloat16 hh0, mm0, ll0, hh1, mm1, ll1;
    split3(o0, hh0, mm0, ll0);
    split3(o1, hh1, mm1, ll1);
    g_xhi[base + lane] = hh0;      g_xhi[base + lane + 32] = hh1;
    g_xmi[base + lane] = mm0;      g_xmi[base + lane + 32] = mm1;
    g_xlo[base + lane] = ll0;      g_xlo[base + lane + 32] = ll1;
}

extern "C" void kernel_launch(void* const* d_in, const int* in_sizes, int n_in,
                              void* d_out, int out_size) {
    const float* hs  = (const float*)d_in[0];
    const float* pb  = (const float*)d_in[1];
    const float* Wq  = (const float*)d_in[2];
    const float* Wk  = (const float*)d_in[3];
    const float* Wv  = (const float*)d_in[4];
    const float* Wo  = (const float*)d_in[5];
    const float* Wrq = (const float*)d_in[6];
    const float* Wrk = (const float*)d_in[7];
    const float* bsc = (const float*)d_in[8];
    const float* alo = (const float*)d_in[9];
    float* out = (float*)d_out;

    static cudaStream_t s1 = 0;
    static cudaEvent_t evFork = 0, evQKV = 0, evPB = 0, evLKV = 0, evPK = 0;
    if (!s1) {
        cudaStreamCreateWithFlags(&s1, cudaStreamNonBlocking);
        cudaEventCreateWithFlags(&evFork, cudaEventDisableTiming);
        cudaEventCreateWithFlags(&evQKV,  cudaEventDisableTiming);
        cudaEventCreateWithFlags(&evPB,   cudaEventDisableTiming);
        cudaEventCreateWithFlags(&evLKV,  cudaEventDisableTiming);
        cudaEventCreateWithFlags(&evPK,   cudaEventDisableTiming);
        cudaFuncSetAttribute(sparse_attn_kernel,
                             cudaFuncAttributeMaxDynamicSharedMemorySize, SP_SMEM);
        cudaFuncSetAttribute(mma_gemm_kernel,
                             cudaFuncAttributeMaxDynamicSharedMemorySize, MMA_SMEM);
    }

    void *gq, *gk, *gv, *gkv, *gks, *gxh, *gxm, *gxl, *gwh, *gwm, *gwl;
    cudaGetSymbolAddress(&gq,  g_q);
    cudaGetSymbolAddress(&gk,  g_k);
    cudaGetSymbolAddress(&gv,  g_v);
    cudaGetSymbolAddress(&gkv, g_kv);
    cudaGetSymbolAddress(&gks, g_ksum);
    cudaGetSymbolAddress(&gxh, g_xhi);
    cudaGetSymbolAddress(&gxm, g_xmi);
    cudaGetSymbolAddress(&gxl, g_xlo);
    cudaGetSymbolAddress(&gwh, g_whi);
    cudaGetSymbolAddress(&gwm, g_wmi);
    cudaGetSymbolAddress(&gwl, g_wlo);
    __nv_bfloat16* xhi = (__nv_bfloat16*)gxh;
    __nv_bfloat16* xmi = (__nv_bfloat16*)gxm;
    __nv_bfloat16* xlo = (__nv_bfloat16*)gxl;
    __nv_bfloat16* whi = (__nv_bfloat16*)gwh;
    __nv_bfloat16* wmi = (__nv_bfloat16*)gwm;
    __nv_bfloat16* wlo = (__nv_bfloat16*)gwl;

    // ---- fork: pool_bias depends only on the input tensor ----
    cudaEventRecord(evFork, 0);
    cudaStreamWaitEvent(s1, evFork, 0);
    pool_bias_kernel<<<dim3(NBB*NBB, HH), 128, 0, s1>>>(pb);
    cudaEventRecord(evPB, s1);

    cudaMemsetAsync(gkv, 0, sizeof(float) * BB*HH*DHH*DHH);
    cudaMemsetAsync(gks, 0, sizeof(float) * BB*HH*DHH);

    const int NX4 = BB*LL*DMM/4;
    const int NW4 = DMM*DMM/4;
    cvt3_kernel<<<(NX4+255)/256, 256>>>(hs, xhi, xmi, xlo, NX4);
    cvt3_kernel<<<(NW4+255)/256, 256>>>(Wq, whi,             wmi,             wlo,             NW4);
    cvt3_kernel<<<(NW4+255)/256, 256>>>(Wk, whi +   DMM*DMM, wmi +   DMM*DMM, wlo +   DMM*DMM, NW4);
    cvt3_kernel<<<(NW4+255)/256, 256>>>(Wv, whi + 2*DMM*DMM, wmi + 2*DMM*DMM, wlo + 2*DMM*DMM, NW4);
    cvt3_kernel<<<(NW4+255)/256, 256>>>(Wo, whi + 3*DMM*DMM, wmi + 3*DMM*DMM, wlo + 3*DMM*DMM, NW4);

    // fused QKV via compensated split-bf16 MMA (N=1536, BHLD scatter)
    mma_gemm_kernel<<<dim3(12, 64), 512, MMA_SMEM>>>(
        xhi, xmi, xlo, whi, wmi, wlo, (float*)gq, (float*)gk, (float*)gv, 1);
    cudaEventRecord(evQKV, 0);

    // ---- s1: pack (q8/k8/v-split) then linear_kv, both depend only on QKV output ----
    cudaStreamWaitEvent(s1, evQKV, 0);
    pack_kernel<<<dim3(NBB, BB*HH), 256, 0, s1>>>();
    cudaEventRecord(evPK, s1);
    linear_kv_kernel<<<dim3(LL/256, BB*HH), 256, 0, s1>>>();
    cudaEventRecord(evLKV, s1);

    // ---- s0: router chain + sparse attention (half split, precomputed packs) ----
    pool_proj_kernel<<<dim3(NBB, BB*HH), 256>>>(Wrq, Wrk);
    cudaStreamWaitEvent(0, evPB, 0);
    router_topk_kernel<<<BB*HH, 256>>>(bsc);
    cudaStreamWaitEvent(0, evPK, 0);
    sparse_attn_kernel<<<dim3(NBB, BB*HH, 2), 256, SP_SMEM>>>(pb);

    // ---- join: blend (writes bf16 splits directly) then Wo GEMM ----
    cudaStreamWaitEvent(0, evLKV, 0);
    linear_out_blend_kernel<<<dim3(LL/8, BB*HH), 256>>>(alo);
    mma_gemm_kernel<<<dim3(4, 64), 512, MMA_SMEM>>>(
        xhi, xmi, xlo, whi + 3*DMM*DMM, wmi + 3*DMM*DMM, wlo + 3*DMM*DMM, out, out, out, 0);
}